// round 14
// baseline (speedup 1.0000x reference)
#include <cuda_runtime.h>
#include <cstdint>

// GaussianYOLOLayer: [B, NA*(NC+6), G, G] -> [B, NA*G*G, NC+6]
// B=32, NA=3, NC+6=86, G=76, stride=8.
//   c==0: (sigmoid(v)+i)*8   c==1: (sigmoid(v)+j)*8
//   c==2: exp(v)*116|156|373 c==3: exp(v)*90|198|326   c>=4: sigmoid(v)

#define GDIM 76
#define GG   5776
#define NCH  86
#define NJP  43              // channel pairs
#define TS   64              // spatial positions per tile
#define NANC 3

// sigmoid via MUFU.TANH: sigmoid(v) = 0.5*tanh(0.5*v) + 0.5  (1 MUFU)
__device__ __forceinline__ float tanh_half(float v) {
    float t;
    asm("tanh.approx.f32 %0, %1;" : "=f"(t) : "f"(v * 0.5f));
    return t;
}
__device__ __forceinline__ float fsigmoid(float v) {
    return fmaf(tanh_half(v), 0.5f, 0.5f);
}
// (sigmoid(v) + g) * 8 == tanh(0.5v)*4 + (8g + 4)
__device__ __forceinline__ float sig_grid(float v, float g8p4) {
    return fmaf(tanh_half(v), 4.0f, g8p4);
}

__device__ __forceinline__ uint32_t smem_u32(const void* p) {
    uint32_t a;
    asm("{ .reg .u64 t; cvta.to.shared.u64 t, %1; cvt.u32.u64 %0, t; }"
        : "=r"(a) : "l"(p));
    return a;
}

__global__ __launch_bounds__(256, 8)
void yolo_head_kernel(const float* __restrict__ x, float* __restrict__ out) {
    // PACKED output-order tile: float2 word(s, j) = s*43 + j  (22016 B)
    __shared__ __align__(16) float2 tile2[TS * NJP];

    const int tidx = threadIdx.x;
    const int tblk = blockIdx.x;   // 91 spatial tiles
    const int a    = blockIdx.y;
    const int b    = blockIdx.z;

    const int p0     = tblk * TS;
    const int nvalid = min(TS, GG - p0);   // 64, or 16 on last tile

    const float aw = (a == 0) ? 116.0f : (a == 1) ? 156.0f : 373.0f;
    const float ah = (a == 0) ?  90.0f : (a == 1) ? 198.0f : 326.0f;

    const long long ba = (long long)(b * NANC + a);
    const float4* __restrict__ xin = (const float4*)(x + ba * (long long)NCH * GG);
    const int p4 = p0 >> 2;

    // Two independent 128-thread halves: half 0 -> s in [0,32), half 1 -> [32,64)
    // Per-warp loads stay 128B-per-channel-row (8 consecutive float4 per warp).
    const int half = tidx >> 7;       // 0 or 1
    const int ht   = tidx & 127;
    const int u    = (half << 3) + (ht & 7);   // float4 index 0..15 (global)
    const int s    = u << 2;                   // spatial base

    // ====== Phase A: paired-channel LDG.128, transform, packed STS.64 ======
    if (s < nvalid) {
        #pragma unroll
        for (int it = 0; it < 3; ++it) {
            const int jj = (ht >> 3) + 16 * it;   // channel pair 0..47
            if (jj < NJP) {
                const int c0 = 2 * jj;
                const float4 vl = xin[c0 * (GG / 4) + p4 + u];
                const float4 vh = xin[(c0 + 1) * (GG / 4) + p4 + u];
                float2 r0, r1, r2, r3;   // (lo=c0, hi=c0+1) per s+k
                if (jj >= 2) {
                    r0 = make_float2(fsigmoid(vl.x), fsigmoid(vh.x));
                    r1 = make_float2(fsigmoid(vl.y), fsigmoid(vh.y));
                    r2 = make_float2(fsigmoid(vl.z), fsigmoid(vh.z));
                    r3 = make_float2(fsigmoid(vl.w), fsigmoid(vh.w));
                } else if (jj == 0) {
                    const int p  = p0 + s;
                    const int j0 = p / GDIM;
                    const int i0 = p - j0 * GDIM;
                    int i1 = i0 + 1, j1 = j0; if (i1 >= GDIM) { i1 = 0; j1++; }
                    int i2 = i1 + 1, j2 = j1; if (i2 >= GDIM) { i2 = 0; j2++; }
                    int i3 = i2 + 1, j3 = j2; if (i3 >= GDIM) { i3 = 0; j3++; }
                    r0 = make_float2(sig_grid(vl.x, 8.0f * i0 + 4.0f),
                                     sig_grid(vh.x, 8.0f * j0 + 4.0f));
                    r1 = make_float2(sig_grid(vl.y, 8.0f * i1 + 4.0f),
                                     sig_grid(vh.y, 8.0f * j1 + 4.0f));
                    r2 = make_float2(sig_grid(vl.z, 8.0f * i2 + 4.0f),
                                     sig_grid(vh.z, 8.0f * j2 + 4.0f));
                    r3 = make_float2(sig_grid(vl.w, 8.0f * i3 + 4.0f),
                                     sig_grid(vh.w, 8.0f * j3 + 4.0f));
                } else { // jj == 1: c=2 (w), c=3 (h)
                    r0 = make_float2(__expf(vl.x) * aw, __expf(vh.x) * ah);
                    r1 = make_float2(__expf(vl.y) * aw, __expf(vh.y) * ah);
                    r2 = make_float2(__expf(vl.z) * aw, __expf(vh.z) * ah);
                    r3 = make_float2(__expf(vl.w) * aw, __expf(vh.w) * ah);
                }
                tile2[(s + 0) * NJP + jj] = r0;
                tile2[(s + 1) * NJP + jj] = r1;
                tile2[(s + 2) * NJP + jj] = r2;
                tile2[(s + 3) * NJP + jj] = r3;
            }
        }
    }

    // ====== Phase B: per-half named barrier + async bulk store =============
    // wait_group.read: only wait until SMEM source reads are done (safe for
    // smem reuse by successor CTA); the write completes asynchronously.
    const long long out_base = (ba * (long long)GG + p0) * NCH;

    if (half == 0) {
        asm volatile("bar.sync 1, 128;" ::: "memory");
        if (ht == 0) {
            const int n0 = min(nvalid, 32);
            float* dst = out + out_base;
            const uint32_t src   = smem_u32(tile2);
            const uint32_t bytes = (uint32_t)(n0 * NCH * 4);
            asm volatile("fence.proxy.async.shared::cta;" ::: "memory");
            asm volatile(
                "cp.async.bulk.global.shared::cta.bulk_group [%0], [%1], %2;"
                :: "l"(dst), "r"(src), "r"(bytes) : "memory");
            asm volatile("cp.async.bulk.commit_group;" ::: "memory");
            asm volatile("cp.async.bulk.wait_group.read 0;" ::: "memory");
        }
    } else {
        asm volatile("bar.sync 2, 128;" ::: "memory");
        if (ht == 0 && nvalid > 32) {
            const int n1 = nvalid - 32;
            float* dst = out + out_base + 32 * NCH;
            const uint32_t src   = smem_u32(tile2 + 32 * NJP);
            const uint32_t bytes = (uint32_t)(n1 * NCH * 4);
            asm volatile("fence.proxy.async.shared::cta;" ::: "memory");
            asm volatile(
                "cp.async.bulk.global.shared::cta.bulk_group [%0], [%1], %2;"
                :: "l"(dst), "r"(src), "r"(bytes) : "memory");
            asm volatile("cp.async.bulk.commit_group;" ::: "memory");
            asm volatile("cp.async.bulk.wait_group.read 0;" ::: "memory");
        }
    }
}

extern "C" void kernel_launch(void* const* d_in, const int* in_sizes, int n_in,
                              void* d_out, int out_size) {
    const float* x = (const float*)d_in[0];
    float* out = (float*)d_out;

    const int ntiles = (GG + TS - 1) / TS;  // 91
    dim3 grid(ntiles, NANC, 32);
    yolo_head_kernel<<<grid, 256>>>(x, out);
}

// round 15
// speedup vs baseline: 1.0256x; 1.0256x over previous
#include <cuda_runtime.h>
#include <cstdint>

// GaussianYOLOLayer: [B, NA*(NC+6), G, G] -> [B, NA*G*G, NC+6]
// B=32, NA=3, NC+6=86, G=76, stride=8.
//   c==0: (sigmoid(v)+i)*8   c==1: (sigmoid(v)+j)*8
//   c==2: exp(v)*116|156|373 c==3: exp(v)*90|198|326   c>=4: sigmoid(v)

#define GDIM 76
#define GG   5776
#define NCH  86
#define NJP  43              // channel pairs
#define TS   64              // spatial positions per tile
#define NANC 3

// sigmoid via MUFU.TANH: sigmoid(v) = 0.5*tanh(0.5*v) + 0.5  (1 MUFU)
__device__ __forceinline__ float tanh_half(float v) {
    float t;
    asm("tanh.approx.f32 %0, %1;" : "=f"(t) : "f"(v * 0.5f));
    return t;
}
__device__ __forceinline__ float fsigmoid(float v) {
    return fmaf(tanh_half(v), 0.5f, 0.5f);
}
// (sigmoid(v) + g) * 8 == tanh(0.5v)*4 + (8g + 4)
__device__ __forceinline__ float sig_grid(float v, float g8p4) {
    return fmaf(tanh_half(v), 4.0f, g8p4);
}

__device__ __forceinline__ uint32_t smem_u32(const void* p) {
    uint32_t a;
    asm("{ .reg .u64 t; cvta.to.shared.u64 t, %1; cvt.u32.u64 %0, t; }"
        : "=r"(a) : "l"(p));
    return a;
}

struct XformCtx {
    int p0, s;
    float aw, ah;
};

// Transform one (vl, vh) channel-pair of 4 spatial values and store packed.
__device__ __forceinline__ void xform_store(
    float2* __restrict__ tile2, const XformCtx& cx,
    int jj, float4 vl, float4 vh)
{
    float2 r0, r1, r2, r3;
    if (jj >= 2) {
        r0 = make_float2(fsigmoid(vl.x), fsigmoid(vh.x));
        r1 = make_float2(fsigmoid(vl.y), fsigmoid(vh.y));
        r2 = make_float2(fsigmoid(vl.z), fsigmoid(vh.z));
        r3 = make_float2(fsigmoid(vl.w), fsigmoid(vh.w));
    } else if (jj == 0) {
        const int p  = cx.p0 + cx.s;
        const int j0 = p / GDIM;
        const int i0 = p - j0 * GDIM;
        int i1 = i0 + 1, j1 = j0; if (i1 >= GDIM) { i1 = 0; j1++; }
        int i2 = i1 + 1, j2 = j1; if (i2 >= GDIM) { i2 = 0; j2++; }
        int i3 = i2 + 1, j3 = j2; if (i3 >= GDIM) { i3 = 0; j3++; }
        r0 = make_float2(sig_grid(vl.x, 8.0f * i0 + 4.0f),
                         sig_grid(vh.x, 8.0f * j0 + 4.0f));
        r1 = make_float2(sig_grid(vl.y, 8.0f * i1 + 4.0f),
                         sig_grid(vh.y, 8.0f * j1 + 4.0f));
        r2 = make_float2(sig_grid(vl.z, 8.0f * i2 + 4.0f),
                         sig_grid(vh.z, 8.0f * j2 + 4.0f));
        r3 = make_float2(sig_grid(vl.w, 8.0f * i3 + 4.0f),
                         sig_grid(vh.w, 8.0f * j3 + 4.0f));
    } else { // jj == 1: c=2 (w), c=3 (h)
        r0 = make_float2(__expf(vl.x) * cx.aw, __expf(vh.x) * cx.ah);
        r1 = make_float2(__expf(vl.y) * cx.aw, __expf(vh.y) * cx.ah);
        r2 = make_float2(__expf(vl.z) * cx.aw, __expf(vh.z) * cx.ah);
        r3 = make_float2(__expf(vl.w) * cx.aw, __expf(vh.w) * cx.ah);
    }
    const int base = cx.s * NJP + jj;
    tile2[base          ] = r0;
    tile2[base + NJP    ] = r1;
    tile2[base + 2 * NJP] = r2;
    tile2[base + 3 * NJP] = r3;
}

__global__ __launch_bounds__(256, 7)
void yolo_head_kernel(const float* __restrict__ x, float* __restrict__ out) {
    // PACKED output-order tile: float2 word(s, j) = s*43 + j  (22016 B)
    __shared__ __align__(16) float2 tile2[TS * NJP];

    const int tidx = threadIdx.x;
    const int tblk = blockIdx.x;   // 91 spatial tiles
    const int a    = blockIdx.y;
    const int b    = blockIdx.z;

    const int p0     = tblk * TS;
    const int nvalid = min(TS, GG - p0);   // 64, or 16 on last tile

    XformCtx cx;
    cx.p0 = p0;
    cx.aw = (a == 0) ? 116.0f : (a == 1) ? 156.0f : 373.0f;
    cx.ah = (a == 0) ?  90.0f : (a == 1) ? 198.0f : 326.0f;

    const long long ba = (long long)(b * NANC + a);
    const float4* __restrict__ xin = (const float4*)(x + ba * (long long)NCH * GG);
    const int p4 = p0 >> 2;

    // Two independent 128-thread halves: half 0 -> s in [0,32), half 1 -> [32,64)
    const int half = tidx >> 7;       // 0 or 1
    const int ht   = tidx & 127;
    const int u    = (half << 3) + (ht & 7);   // float4 index 0..15 (global)
    cx.s = u << 2;                             // spatial base

    // ====== Phase A: batched LDG.128 (4 in flight), transform, STS.64 ======
    const int jj0 = ht >> 3;          // 0..15  (always < NJP)
    const int jj1 = jj0 + 16;         // 16..31 (always < NJP)
    const int jj2 = jj0 + 32;         // 32..47 (guarded)

    if (cx.s < nvalid) {
        // front-batch four independent LDG.128 (iterations 0 and 1)
        const float4 vl0 = xin[(2 * jj0    ) * (GG / 4) + p4 + u];
        const float4 vh0 = xin[(2 * jj0 + 1) * (GG / 4) + p4 + u];
        const float4 vl1 = xin[(2 * jj1    ) * (GG / 4) + p4 + u];
        const float4 vh1 = xin[(2 * jj1 + 1) * (GG / 4) + p4 + u];

        xform_store(tile2, cx, jj0, vl0, vh0);
        xform_store(tile2, cx, jj1, vl1, vh1);

        if (jj2 < NJP) {
            const float4 vl2 = xin[(2 * jj2    ) * (GG / 4) + p4 + u];
            const float4 vh2 = xin[(2 * jj2 + 1) * (GG / 4) + p4 + u];
            xform_store(tile2, cx, jj2, vl2, vh2);
        }
    }

    // ====== Phase B: per-half named barrier + async bulk store =============
    const long long out_base = (ba * (long long)GG + p0) * NCH;

    if (half == 0) {
        asm volatile("bar.sync 1, 128;" ::: "memory");
        if (ht == 0) {
            const int n0 = min(nvalid, 32);
            float* dst = out + out_base;
            const uint32_t src   = smem_u32(tile2);
            const uint32_t bytes = (uint32_t)(n0 * NCH * 4);
            asm volatile("fence.proxy.async.shared::cta;" ::: "memory");
            asm volatile(
                "cp.async.bulk.global.shared::cta.bulk_group [%0], [%1], %2;"
                :: "l"(dst), "r"(src), "r"(bytes) : "memory");
            asm volatile("cp.async.bulk.commit_group;" ::: "memory");
            asm volatile("cp.async.bulk.wait_group 0;" ::: "memory");
        }
    } else {
        asm volatile("bar.sync 2, 128;" ::: "memory");
        if (ht == 0 && nvalid > 32) {
            const int n1 = nvalid - 32;
            float* dst = out + out_base + 32 * NCH;
            const uint32_t src   = smem_u32(tile2 + 32 * NJP);
            const uint32_t bytes = (uint32_t)(n1 * NCH * 4);
            asm volatile("fence.proxy.async.shared::cta;" ::: "memory");
            asm volatile(
                "cp.async.bulk.global.shared::cta.bulk_group [%0], [%1], %2;"
                :: "l"(dst), "r"(src), "r"(bytes) : "memory");
            asm volatile("cp.async.bulk.commit_group;" ::: "memory");
            asm volatile("cp.async.bulk.wait_group 0;" ::: "memory");
        }
    }
}

extern "C" void kernel_launch(void* const* d_in, const int* in_sizes, int n_in,
                              void* d_out, int out_size) {
    const float* x = (const float*)d_in[0];
    float* out = (float*)d_out;

    const int ntiles = (GG + TS - 1) / TS;  // 91
    dim3 grid(ntiles, NANC, 32);
    yolo_head_kernel<<<grid, 256>>>(x, out);
}